// round 6
// baseline (speedup 1.0000x reference)
#include <cuda_runtime.h>
#include <cuda.h>
#include <math.h>
#include <stdint.h>

#define BATCH   32
#define LAYERS  32
#define DIM     4096
#define SELK    24
#define NCHOICE 9
#define GS_EPS  1e-10f

#define LAYER_BYTES (DIM * 4)          // 16384 B per layer
#define PAIR_BYTES  (2 * LAYER_BYTES)  // 32768 B per block

__device__ __forceinline__ uint32_t smem_u32(const void* p) {
    uint32_t a;
    asm("{ .reg .u64 t; cvta.to.shared.u64 t, %1; cvt.u32.u64 %0, t; }"
        : "=r"(a) : "l"(p));
    return a;
}

// Block = (batch, layer-pair). One warp. TMA bulk-in both layers (no idx
// dependency, issued immediately), argmax overlaps TMA latency, then
// conditional TMA bulk-out of layers inside the selected window.
__global__ void __launch_bounds__(32)
tma_gather_kernel(const char* __restrict__ feats,
                  const float* __restrict__ logits,
                  const float* __restrict__ noise,
                  char* __restrict__ out) {
    __shared__ alignas(128) char buf[PAIR_BYTES];
    __shared__ alignas(8) unsigned long long mbar;

    const int b    = blockIdx.y;
    const int lp   = blockIdx.x;          // pair 0..15 -> layers 2lp, 2lp+1
    const int lane = threadIdx.x;
    const int l0   = lp * 2;

    const uint32_t s_buf  = smem_u32(buf);
    const uint32_t s_mbar = smem_u32(&mbar);

    // ---- issue TMA-in ASAP (idx-independent) ----
    if (lane == 0) {
        asm volatile("mbarrier.init.shared.b64 [%0], 1;" :: "r"(s_mbar) : "memory");
        asm volatile("fence.mbarrier_init.release.cluster;" ::: "memory");
        asm volatile("mbarrier.arrive.expect_tx.shared.b64 _, [%0], %1;"
                     :: "r"(s_mbar), "r"((uint32_t)PAIR_BYTES) : "memory");
        const char* src = feats + ((size_t)b * LAYERS + l0) * LAYER_BYTES;
        asm volatile("cp.async.bulk.shared::cta.global.mbarrier::complete_tx::bytes "
                     "[%0], [%1], %2, [%3];"
                     :: "r"(s_buf), "l"(src), "r"((uint32_t)LAYER_BYTES),
                        "r"(s_mbar) : "memory");
        asm volatile("cp.async.bulk.shared::cta.global.mbarrier::complete_tx::bytes "
                     "[%0], [%1], %2, [%3];"
                     :: "r"(s_buf + LAYER_BYTES), "l"(src + LAYER_BYTES),
                        "r"((uint32_t)LAYER_BYTES), "r"(s_mbar) : "memory");
    }

    // ---- Gumbel argmax (lanes 0-8), overlapped with TMA latency ----
    float v  = -INFINITY;
    int   bc = lane;
    if (lane < NCHOICE) {
        float u = __ldg(&noise[b * NCHOICE + lane]);
        float g = -logf(-logf(u + GS_EPS) + GS_EPS);
        v = __ldg(&logits[lane]) + g;     // tau=1; softmax monotone -> same argmax
    }
    #pragma unroll
    for (int off = 16; off; off >>= 1) {
        float ov = __shfl_down_sync(0xffffffffu, v,  off);
        int   oc = __shfl_down_sync(0xffffffffu, bc, off);
        if (ov > v || (ov == v && oc < bc)) { v = ov; bc = oc; }  // first-max wins
    }
    const int idx = __shfl_sync(0xffffffffu, bc, 0);

    // one-hot selection_probs tail (one block per batch)
    if (lp == 0 && lane < NCHOICE) {
        ((float*)out)[(size_t)BATCH * SELK * DIM + b * NCHOICE + lane] =
            (lane == idx) ? 1.0f : 0.0f;
    }

    // ---- wait for TMA-in, then conditional TMA-out ----
    if (lane == 0) {
        // parity-0 wait loop (barrier used exactly once per block)
        asm volatile(
            "{\n\t"
            ".reg .pred P;\n\t"
            "W%=:\n\t"
            "mbarrier.try_wait.parity.shared.b64 P, [%0], 0, 0x989680;\n\t"
            "@P bra D%=;\n\t"
            "bra W%=;\n\t"
            "D%=:\n\t"
            "}" :: "r"(s_mbar) : "memory");

        asm volatile("fence.proxy.async;" ::: "memory");

        const unsigned rel0 = (unsigned)(l0 - idx);
        if (rel0 < SELK) {
            char* dst = out + ((size_t)b * SELK + rel0) * LAYER_BYTES;
            asm volatile("cp.async.bulk.global.shared::cta.bulk_group [%0], [%1], %2;"
                         :: "l"(dst), "r"(s_buf), "r"((uint32_t)LAYER_BYTES)
                         : "memory");
        }
        const unsigned rel1 = (unsigned)(l0 + 1 - idx);
        if (rel1 < SELK) {
            char* dst = out + ((size_t)b * SELK + rel1) * LAYER_BYTES;
            asm volatile("cp.async.bulk.global.shared::cta.bulk_group [%0], [%1], %2;"
                         :: "l"(dst), "r"(s_buf + LAYER_BYTES),
                            "r"((uint32_t)LAYER_BYTES) : "memory");
        }
        asm volatile("cp.async.bulk.commit_group;" ::: "memory");
        asm volatile("cp.async.bulk.wait_group 0;" ::: "memory");
    }
}

extern "C" void kernel_launch(void* const* d_in, const int* in_sizes, int n_in,
                              void* d_out, int out_size) {
    const char*  feats  = (const char*)d_in[0];
    const float* logits = (const float*)d_in[1];
    const float* noise  = (const float*)d_in[2];
    char*        out    = (char*)d_out;

    dim3 grid(LAYERS / 2, BATCH);        // (16, 32) = 512 blocks, 1 warp each
    tma_gather_kernel<<<grid, 32>>>(feats, logits, noise, out);
}

// round 7
// speedup vs baseline: 1.0036x; 1.0036x over previous
#include <cuda_runtime.h>
#include <math.h>

#define BATCH   32
#define LAYERS  32
#define DIM     4096
#define SELK    24
#define NCHOICE 9
#define GS_EPS  1e-10f

#define F4_PER_LAYER (DIM / 4)      // 1024 float4 per layer

// Minimal-traffic dependent gather (12 MB read + 12 MB write = floor) with
// maximal latency tolerance: block = (batch, 3 output layers), 256 threads,
// 12 independent LDG.128 in flight per thread before any store. 256 blocks
// -> <=2 blocks/SM, single wave, negligible launch + cross-CTA queue effects.

__global__ void __launch_bounds__(256)
gather3_kernel(const float4* __restrict__ feats4,
               const float*  __restrict__ logits,
               const float*  __restrict__ noise,
               float* __restrict__ out) {
    const int b  = blockIdx.y;
    const int k0 = blockIdx.x * 3;        // output layers k0..k0+2
    const int t  = threadIdx.x;
    const int lane = t & 31;

    // ---- per-warp Gumbel argmax (lanes 0-8): one L2-hot load + shuffles ----
    float v  = -INFINITY;
    int   bc = lane;
    if (lane < NCHOICE) {
        float u = __ldg(&noise[b * NCHOICE + lane]);
        float g = -logf(-logf(u + GS_EPS) + GS_EPS);
        v = __ldg(&logits[lane]) + g;     // tau=1; softmax monotone -> same argmax
    }
    #pragma unroll
    for (int off = 16; off; off >>= 1) {
        float ov = __shfl_down_sync(0xffffffffu, v,  off);
        int   oc = __shfl_down_sync(0xffffffffu, bc, off);
        if (ov > v || (ov == v && oc < bc)) { v = ov; bc = oc; }  // first-max wins
    }
    const int idx = __shfl_sync(0xffffffffu, bc, 0);

    // one-hot selection_probs tail (one block per batch)
    if (blockIdx.x == 0 && t < NCHOICE) {
        out[(size_t)BATCH * SELK * DIM + b * NCHOICE + t] =
            (t == idx) ? 1.0f : 0.0f;
    }

    // ---- 3 layers: issue all 12 loads (MLP=12), then all 12 stores ----
    const float4* __restrict__ src =
        feats4 + ((size_t)b * LAYERS + idx + k0) * F4_PER_LAYER;
    float4* __restrict__ dst =
        (float4*)out + ((size_t)b * SELK + k0) * F4_PER_LAYER;

    float4 r[3][4];
    #pragma unroll
    for (int j = 0; j < 3; j++) {
        const float4* s = src + (size_t)j * F4_PER_LAYER;
        #pragma unroll
        for (int q = 0; q < 4; q++)
            r[j][q] = __ldg(&s[t + q * 256]);
    }
    #pragma unroll
    for (int j = 0; j < 3; j++) {
        float4* d = dst + (size_t)j * F4_PER_LAYER;
        #pragma unroll
        for (int q = 0; q < 4; q++)
            __stcs(&d[t + q * 256], r[j][q]);
    }
}

extern "C" void kernel_launch(void* const* d_in, const int* in_sizes, int n_in,
                              void* d_out, int out_size) {
    const float* feats  = (const float*)d_in[0];
    const float* logits = (const float*)d_in[1];
    const float* noise  = (const float*)d_in[2];
    float*       out    = (float*)d_out;

    dim3 grid(SELK / 3, BATCH);           // (8, 32) = 256 blocks
    gather3_kernel<<<grid, 256>>>((const float4*)feats, logits, noise, out);
}

// round 8
// speedup vs baseline: 1.0811x; 1.0772x over previous
#include <cuda_runtime.h>
#include <math.h>

#define BATCH   32
#define LAYERS  32
#define DIM     4096
#define SELK    24
#define NCHOICE 9
#define GS_EPS  1e-10f

#define F4_PER_LAYER (DIM / 4)      // 1024 float4 per layer

// Block = one (batch, layer). Feature loads are idx-independent and issue in
// the first instructions; each warp computes the 9-way Gumbel argmax itself
// (shuffle reduce, overlapped under its own load latency) -> no __syncthreads,
// no cross-warp coupling. Store is block-uniform predicated (keep layer iff
// idx <= l < idx+24), streaming (.cs) so the output never evicts the
// L2-resident input across graph replays.

__global__ void __launch_bounds__(256)
fused_kernel(const float4* __restrict__ feats4,
             const float*  __restrict__ logits,
             const float*  __restrict__ noise,
             float* __restrict__ out) {
    const int b = blockIdx.y;
    const int l = blockIdx.x;             // layer 0..31
    const int t = threadIdx.x;
    const int lane = t & 31;

    // ---- feature loads first: 4 independent LDG.128, zero idx dependency ----
    const float4* __restrict__ src =
        feats4 + ((size_t)b * LAYERS + l) * F4_PER_LAYER;
    float4 v0 = __ldg(&src[t]);
    float4 v1 = __ldg(&src[t + 256]);
    float4 v2 = __ldg(&src[t + 512]);
    float4 v3 = __ldg(&src[t + 768]);

    // ---- per-warp Gumbel argmax (lanes 0-8), overlapped with load latency ----
    float v  = -INFINITY;
    int   bc = lane;
    if (lane < NCHOICE) {
        float u = __ldg(&noise[b * NCHOICE + lane]);
        float g = -logf(-logf(u + GS_EPS) + GS_EPS);
        v = __ldg(&logits[lane]) + g;     // tau=1; softmax monotone -> same argmax
    }
    #pragma unroll
    for (int off = 16; off; off >>= 1) {
        float ov = __shfl_down_sync(0xffffffffu, v,  off);
        int   oc = __shfl_down_sync(0xffffffffu, bc, off);
        if (ov > v || (ov == v && oc < bc)) { v = ov; bc = oc; }  // first-max wins
    }
    const int idx = __shfl_sync(0xffffffffu, bc, 0);

    // one-hot selection_probs tail (one block per batch)
    if (l == 0 && t < NCHOICE) {
        out[(size_t)BATCH * SELK * DIM + b * NCHOICE + t] =
            (t == idx) ? 1.0f : 0.0f;
    }

    // ---- block-uniform predicated streaming store ----
    const unsigned rel = (unsigned)(l - idx);
    if (rel < SELK) {
        float4* __restrict__ dst =
            (float4*)out + ((size_t)b * SELK + rel) * F4_PER_LAYER;
        __stcs(&dst[t],       v0);
        __stcs(&dst[t + 256], v1);
        __stcs(&dst[t + 512], v2);
        __stcs(&dst[t + 768], v3);
    }
}

extern "C" void kernel_launch(void* const* d_in, const int* in_sizes, int n_in,
                              void* d_out, int out_size) {
    const float* feats  = (const float*)d_in[0];
    const float* logits = (const float*)d_in[1];
    const float* noise  = (const float*)d_in[2];
    float*       out    = (float*)d_out;

    dim3 grid(LAYERS, BATCH);             // 1024 blocks, one per (layer, batch)
    fused_kernel<<<grid, 256>>>((const float4*)feats, logits, noise, out);
}